// round 4
// baseline (speedup 1.0000x reference)
#include <cuda_runtime.h>
#include <math.h>

#define BB 32
#define LL 512
#define DD 1024
#define EE 8
#define HH 16
#define HD 64

// Scratch (device globals — no allocation allowed)
__device__ float g_q[BB * LL * DD];
__device__ float g_k[BB * LL * DD];
__device__ float g_v[BB * LL * DD];
__device__ float g_ctx[BB * LL * DD];
__device__ int g_routes[BB];

// ---------------------------------------------------------------------------
// Router: mean-pool over L, logits = mean @ router_w + b, softmax -> probs,
// argmax -> g_routes. One block per batch.
// ---------------------------------------------------------------------------
__global__ void router_kernel(const float* __restrict__ x,
                              const float* __restrict__ rw,
                              const float* __restrict__ rb,
                              float* __restrict__ probs) {
    int b = blockIdx.x;
    __shared__ float mean[DD];
    __shared__ float logits[EE];
    const float* xb = x + (size_t)b * LL * DD;
    for (int d = threadIdx.x; d < DD; d += blockDim.x) {
        float s = 0.f;
        for (int l = 0; l < LL; l++) s += xb[(size_t)l * DD + d];
        mean[d] = s * (1.0f / LL);
    }
    __syncthreads();
    int w = threadIdx.x >> 5, lane = threadIdx.x & 31;
    if (w < EE) {
        float s = 0.f;
        for (int d = lane; d < DD; d += 32) s += mean[d] * rw[d * EE + w];
        for (int o = 16; o; o >>= 1) s += __shfl_xor_sync(0xffffffffu, s, o);
        if (lane == 0) logits[w] = s + rb[w];
    }
    __syncthreads();
    if (threadIdx.x == 0) {
        float mx = logits[0];
        int am = 0;
        for (int e = 1; e < EE; e++)
            if (logits[e] > mx) { mx = logits[e]; am = e; }
        float ex[EE];
        float den = 0.f;
        for (int e = 0; e < EE; e++) { ex[e] = expf(logits[e] - mx); den += ex[e]; }
        float inv = 1.0f / den;
        for (int e = 0; e < EE; e++) probs[b * EE + e] = ex[e] * inv;
        g_routes[b] = am;
    }
}

// ---------------------------------------------------------------------------
// Routed SGEMM: C[b] = A[b] (LLxDD) @ W[route[b]] (DDxDD).
// 128x128 block tile, BK=8, 256 threads, 8x8 microtile (split-vector layout).
// ---------------------------------------------------------------------------
__global__ __launch_bounds__(256, 2) void gemm_routed(
    const float* __restrict__ A, const float* __restrict__ W,
    float* __restrict__ C) {
    __shared__ float As[8][128];
    __shared__ float Bs[8][128];
    int b = blockIdx.z;
    const float* Ab = A + (size_t)b * LL * DD;
    const float* Wb = W + (size_t)g_routes[b] * DD * DD;
    float* Cb = C + (size_t)b * LL * DD;
    int tM = blockIdx.y * 128, tN = blockIdx.x * 128;
    int tid = threadIdx.x;
    int tx = tid & 15, ty = tid >> 4;
    int ar = tid >> 1;        // A load: row 0..127
    int ak = (tid & 1) * 4;   // A load: k group 0 or 4
    int br = tid >> 5;        // B load: k row 0..7
    int bc = (tid & 31) * 4;  // B load: n col group

    float acc[8][8];
#pragma unroll
    for (int i = 0; i < 8; i++)
#pragma unroll
        for (int j = 0; j < 8; j++) acc[i][j] = 0.f;

    for (int k0 = 0; k0 < DD; k0 += 8) {
        float4 av = *(const float4*)&Ab[(size_t)(tM + ar) * DD + k0 + ak];
        float4 bv = *(const float4*)&Wb[(size_t)(k0 + br) * DD + tN + bc];
        __syncthreads();  // previous iteration's compute done
        As[ak + 0][ar] = av.x;
        As[ak + 1][ar] = av.y;
        As[ak + 2][ar] = av.z;
        As[ak + 3][ar] = av.w;
        *(float4*)&Bs[br][bc] = bv;
        __syncthreads();
#pragma unroll
        for (int kk = 0; kk < 8; kk++) {
            float a[8], bbv[8];
            *(float4*)&a[0] = *(const float4*)&As[kk][ty * 4];
            *(float4*)&a[4] = *(const float4*)&As[kk][64 + ty * 4];
            *(float4*)&bbv[0] = *(const float4*)&Bs[kk][tx * 4];
            *(float4*)&bbv[4] = *(const float4*)&Bs[kk][64 + tx * 4];
#pragma unroll
            for (int i = 0; i < 8; i++)
#pragma unroll
                for (int j = 0; j < 8; j++) acc[i][j] += a[i] * bbv[j];
        }
    }
#pragma unroll
    for (int i = 0; i < 8; i++) {
        int row = (i < 4) ? (ty * 4 + i) : (64 + ty * 4 + (i - 4));
        float* cp = &Cb[(size_t)(tM + row) * DD + tN];
        *(float4*)&cp[tx * 4] =
            make_float4(acc[i][0], acc[i][1], acc[i][2], acc[i][3]);
        *(float4*)&cp[64 + tx * 4] =
            make_float4(acc[i][4], acc[i][5], acc[i][6], acc[i][7]);
    }
}

// ---------------------------------------------------------------------------
// RoPE (interleaved), applied in-place to g_q and g_k.
// ---------------------------------------------------------------------------
__global__ void rope_kernel() {
    int idx = blockIdx.x * blockDim.x + threadIdx.x;
    int total = BB * LL * HH * (HD / 2);
    if (idx >= total) return;
    int d2 = idx & 31;
    int h = (idx >> 5) & 15;
    int l = (idx >> 9) & 511;
    int b = idx >> 18;
    float inv = powf(10000.0f, -(float)d2 / 32.0f);
    float ang = (float)l * inv;
    float s, c;
    sincosf(ang, &s, &c);
    size_t base = ((size_t)(b * LL + l)) * DD + h * HD + 2 * d2;
    float2 q = *(float2*)&g_q[base];
    float2 k = *(float2*)&g_k[base];
    *(float2*)&g_q[base] = make_float2(q.x * c - q.y * s, q.y * c + q.x * s);
    *(float2*)&g_k[base] = make_float2(k.x * c - k.y * s, k.y * c + k.x * s);
}

// ---------------------------------------------------------------------------
// Flash-style causal attention: one block per (q-tile 64, head, batch).
// Online softmax; O accumulated in registers (thread = (row, 16-col slice)).
// Writes g_ctx in [B, L, D] layout (head transposed back).
// ---------------------------------------------------------------------------
__global__ __launch_bounds__(256) void attn_kernel() {
    extern __shared__ float smem[];
    float* sQ = smem;             // [64][65]  (row-major, padded)
    float* sK = sQ + 64 * 65;     // [64][65]
    float* sV = sK + 64 * 65;     // [64][64]
    float* sP = sV + 64 * 64;     // [64][65]
    int qt = blockIdx.x, h = blockIdx.y, b = blockIdx.z;
    int tid = threadIdx.x;
    const float scale = 0.125f;  // 1/sqrt(64)
    size_t hbase = ((size_t)b * LL) * DD + h * HD;

    // Load Q tile
    for (int i = tid; i < 64 * 16; i += 256) {
        int r = i >> 4, cg = (i & 15) * 4;
        float4 v = *(const float4*)&g_q[hbase + (size_t)(qt * 64 + r) * DD + cg];
        sQ[r * 65 + cg + 0] = v.x;
        sQ[r * 65 + cg + 1] = v.y;
        sQ[r * 65 + cg + 2] = v.z;
        sQ[r * 65 + cg + 3] = v.w;
    }

    int r = tid >> 2;   // output row 0..63
    int c4 = tid & 3;   // 16-wide col slice within hd
    int tx = tid & 15, ty = tid >> 4;
    float o[16];
#pragma unroll
    for (int i = 0; i < 16; i++) o[i] = 0.f;
    float m_i = -1e30f, l_i = 0.f;

    for (int kt = 0; kt <= qt; kt++) {
        __syncthreads();  // previous iteration's consumers done
        for (int i = tid; i < 64 * 16; i += 256) {
            int rr = i >> 4, cg = (i & 15) * 4;
            size_t g = hbase + (size_t)(kt * 64 + rr) * DD + cg;
            float4 kv = *(const float4*)&g_k[g];
            sK[rr * 65 + cg + 0] = kv.x;
            sK[rr * 65 + cg + 1] = kv.y;
            sK[rr * 65 + cg + 2] = kv.z;
            sK[rr * 65 + cg + 3] = kv.w;
            *(float4*)&sV[rr * 64 + cg] = *(const float4*)&g_v[g];
        }
        __syncthreads();

        // S = Q @ K^T (16x16 threads, 4x4 microtile)
        float acc[4][4];
#pragma unroll
        for (int i = 0; i < 4; i++)
#pragma unroll
            for (int j = 0; j < 4; j++) acc[i][j] = 0.f;
        for (int kk = 0; kk < 64; kk++) {
            float a[4], bb[4];
#pragma unroll
            for (int i = 0; i < 4; i++) a[i] = sQ[(ty * 4 + i) * 65 + kk];
#pragma unroll
            for (int j = 0; j < 4; j++) bb[j] = sK[(tx * 4 + j) * 65 + kk];
#pragma unroll
            for (int i = 0; i < 4; i++)
#pragma unroll
                for (int j = 0; j < 4; j++) acc[i][j] += a[i] * bb[j];
        }
        bool diag = (kt == qt);
#pragma unroll
        for (int i = 0; i < 4; i++) {
            int sr = ty * 4 + i;
#pragma unroll
            for (int j = 0; j < 4; j++) {
                int sc = tx * 4 + j;
                float vv = acc[i][j] * scale;
                if (diag && sc > sr) vv = -1e30f;
                sP[sr * 65 + sc] = vv;
            }
        }
        __syncthreads();

        // Online softmax: group of 4 lanes per row
        float mloc = -1e30f;
#pragma unroll
        for (int jj = 0; jj < 16; jj++)
            mloc = fmaxf(mloc, sP[r * 65 + c4 * 16 + jj]);
        mloc = fmaxf(mloc, __shfl_xor_sync(0xffffffffu, mloc, 1));
        mloc = fmaxf(mloc, __shfl_xor_sync(0xffffffffu, mloc, 2));
        float mnew = fmaxf(m_i, mloc);
        float alpha = __expf(m_i - mnew);
        float psum = 0.f;
#pragma unroll
        for (int jj = 0; jj < 16; jj++) {
            float p = __expf(sP[r * 65 + c4 * 16 + jj] - mnew);
            sP[r * 65 + c4 * 16 + jj] = p;
            psum += p;
        }
        psum += __shfl_xor_sync(0xffffffffu, psum, 1);
        psum += __shfl_xor_sync(0xffffffffu, psum, 2);
        l_i = l_i * alpha + psum;
        m_i = mnew;
#pragma unroll
        for (int i = 0; i < 16; i++) o[i] *= alpha;
        __syncwarp();  // row written by 4 lanes of this warp

        // O += P @ V
        for (int j = 0; j < 64; j++) {
            float p = sP[r * 65 + j];
            float4 v0 = *(const float4*)&sV[j * 64 + c4 * 16 + 0];
            float4 v1 = *(const float4*)&sV[j * 64 + c4 * 16 + 4];
            float4 v2 = *(const float4*)&sV[j * 64 + c4 * 16 + 8];
            float4 v3 = *(const float4*)&sV[j * 64 + c4 * 16 + 12];
            o[0] += p * v0.x;  o[1] += p * v0.y;  o[2] += p * v0.z;  o[3] += p * v0.w;
            o[4] += p * v1.x;  o[5] += p * v1.y;  o[6] += p * v1.z;  o[7] += p * v1.w;
            o[8] += p * v2.x;  o[9] += p * v2.y;  o[10] += p * v2.z; o[11] += p * v2.w;
            o[12] += p * v3.x; o[13] += p * v3.y; o[14] += p * v3.z; o[15] += p * v3.w;
        }
    }

    float invl = 1.0f / l_i;
    size_t obase = hbase + (size_t)(qt * 64 + r) * DD + c4 * 16;
#pragma unroll
    for (int i = 0; i < 16; i += 4)
        *(float4*)&g_ctx[obase + i] =
            make_float4(o[i] * invl, o[i + 1] * invl, o[i + 2] * invl,
                        o[i + 3] * invl);
}

// ---------------------------------------------------------------------------
extern "C" void kernel_launch(void* const* d_in, const int* in_sizes, int n_in,
                              void* d_out, int out_size) {
    (void)in_sizes; (void)n_in; (void)out_size;
    const float* x  = (const float*)d_in[0];
    const float* qw = (const float*)d_in[1];
    const float* kw = (const float*)d_in[2];
    const float* vw = (const float*)d_in[3];
    const float* ow = (const float*)d_in[4];
    const float* rw = (const float*)d_in[5];
    const float* rb = (const float*)d_in[6];
    float* out = (float*)d_out;
    float* probs = out + (size_t)BB * LL * DD;  // tuple tail: attn_probs [B, E]

    void *pq, *pk, *pv, *pc;
    cudaGetSymbolAddress(&pq, g_q);
    cudaGetSymbolAddress(&pk, g_k);
    cudaGetSymbolAddress(&pv, g_v);
    cudaGetSymbolAddress(&pc, g_ctx);

    router_kernel<<<BB, 256>>>(x, rw, rb, probs);

    dim3 gg(DD / 128, LL / 128, BB);
    gemm_routed<<<gg, 256>>>(x, qw, (float*)pq);
    gemm_routed<<<gg, 256>>>(x, kw, (float*)pk);
    gemm_routed<<<gg, 256>>>(x, vw, (float*)pv);

    int pairs = BB * LL * HH * (HD / 2);
    rope_kernel<<<pairs / 256, 256>>>();

    int smem = (64 * 65 * 2 + 64 * 64 + 64 * 65) * (int)sizeof(float);
    cudaFuncSetAttribute(attn_kernel,
                         cudaFuncAttributeMaxDynamicSharedMemorySize, smem);
    attn_kernel<<<dim3(LL / 64, HH, BB), 256, smem>>>();

    gemm_routed<<<gg, 256>>>((const float*)pc, ow, out);
}

// round 7
// speedup vs baseline: 1.5220x; 1.5220x over previous
#include <cuda_runtime.h>
#include <cuda_bf16.h>
#include <math.h>
#include <stdint.h>

#define BB 32
#define LL 512
#define DD 1024
#define EE 8
#define HH 16
#define HD 64

// ---------------- scratch globals (no allocation allowed) -------------------
__device__ float g_q[BB * LL * DD];
__device__ float g_k[BB * LL * DD];
__device__ float g_v[BB * LL * DD];
__device__ float g_ctx[BB * LL * DD];
__device__ int g_routes[BB];
__device__ __nv_bfloat16 g_ahi[BB * LL * DD];   // split of A operand (x, then ctx)
__device__ __nv_bfloat16 g_alo[BB * LL * DD];
__device__ __nv_bfloat16 g_wthi[4u * EE * DD * DD];  // W^T hi, [proj][expert][N][K]
__device__ __nv_bfloat16 g_wtlo[4u * EE * DD * DD];

// ---------------- PTX helpers (family-agnostic sm_80+ subset) ---------------
__device__ __forceinline__ uint32_t smem_u32(const void* p) {
    uint32_t a;
    asm("{ .reg .u64 t; cvta.to.shared.u64 t, %1; cvt.u32.u64 %0, t; }"
        : "=r"(a) : "l"(p));
    return a;
}
#define CP_ASYNC16(dst, src) \
    asm volatile("cp.async.cg.shared.global [%0], [%1], 16;" \
                 :: "r"(dst), "l"(src))
#define CP_COMMIT() asm volatile("cp.async.commit_group;" ::: "memory")
#define CP_WAIT1() asm volatile("cp.async.wait_group 1;" ::: "memory")
#define CP_WAIT0() asm volatile("cp.async.wait_group 0;" ::: "memory")

#define LDSM_X4(r0, r1, r2, r3, a) \
    asm volatile("ldmatrix.sync.aligned.m8n8.x4.shared.b16 {%0,%1,%2,%3}, [%4];" \
                 : "=r"(r0), "=r"(r1), "=r"(r2), "=r"(r3) : "r"(a))

#define MMA_BF16(c, a, b) \
    asm volatile( \
        "mma.sync.aligned.m16n8k16.row.col.f32.bf16.bf16.f32 " \
        "{%0,%1,%2,%3}, {%4,%5,%6,%7}, {%8,%9}, {%0,%1,%2,%3};" \
        : "+f"((c)[0]), "+f"((c)[1]), "+f"((c)[2]), "+f"((c)[3]) \
        : "r"((a)[0]), "r"((a)[1]), "r"((a)[2]), "r"((a)[3]), \
          "r"((b)[0]), "r"((b)[1]))

// ---------------------------------------------------------------------------
// Router
// ---------------------------------------------------------------------------
__global__ void router_kernel(const float* __restrict__ x,
                              const float* __restrict__ rw,
                              const float* __restrict__ rb,
                              float* __restrict__ probs) {
    int b = blockIdx.x;
    __shared__ float mean[DD];
    __shared__ float logits[EE];
    const float* xb = x + (size_t)b * LL * DD;
    for (int d = threadIdx.x; d < DD; d += blockDim.x) {
        float s = 0.f;
        for (int l = 0; l < LL; l++) s += xb[(size_t)l * DD + d];
        mean[d] = s * (1.0f / LL);
    }
    __syncthreads();
    int w = threadIdx.x >> 5, lane = threadIdx.x & 31;
    if (w < EE) {
        float s = 0.f;
        for (int d = lane; d < DD; d += 32) s += mean[d] * rw[d * EE + w];
        for (int o = 16; o; o >>= 1) s += __shfl_xor_sync(0xffffffffu, s, o);
        if (lane == 0) logits[w] = s + rb[w];
    }
    __syncthreads();
    if (threadIdx.x == 0) {
        float mx = logits[0];
        int am = 0;
        for (int e = 1; e < EE; e++)
            if (logits[e] > mx) { mx = logits[e]; am = e; }
        float ex[EE], den = 0.f;
        for (int e = 0; e < EE; e++) { ex[e] = expf(logits[e] - mx); den += ex[e]; }
        float inv = 1.0f / den;
        for (int e = 0; e < EE; e++) probs[b * EE + e] = ex[e] * inv;
        g_routes[b] = am;
    }
}

// ---------------------------------------------------------------------------
// W transpose + bf16 split: Wt[n][k] = W[k][n] -> (hi, lo)
// ---------------------------------------------------------------------------
__global__ void wsplit_kernel(const float* __restrict__ qw,
                              const float* __restrict__ kw,
                              const float* __restrict__ vw,
                              const float* __restrict__ ow) {
    __shared__ float t[32][33];
    int m = blockIdx.z;
    int p = m >> 3, e = m & 7;
    const float* W = (p == 0 ? qw : p == 1 ? kw : p == 2 ? vw : ow) +
                     (size_t)e * DD * DD;
    int n0 = blockIdx.x * 32, k0 = blockIdx.y * 32;
    int tx = threadIdx.x & 31, ty = threadIdx.x >> 5;
#pragma unroll
    for (int i = 0; i < 32; i += 8)
        t[ty + i][tx] = W[(size_t)(k0 + ty + i) * DD + n0 + tx];
    __syncthreads();
    size_t dbase = (size_t)m * DD * DD;
#pragma unroll
    for (int i = 0; i < 32; i += 8) {
        float a = t[tx][ty + i];
        __nv_bfloat16 hi = __float2bfloat16(a);
        __nv_bfloat16 lo = __float2bfloat16(a - __bfloat162float(hi));
        size_t di = dbase + (size_t)(n0 + ty + i) * DD + k0 + tx;
        g_wthi[di] = hi;
        g_wtlo[di] = lo;
    }
}

// ---------------------------------------------------------------------------
// A-operand bf16 split (x, and later ctx). 4 floats / thread.
// ---------------------------------------------------------------------------
__global__ void asplit_kernel(const float* __restrict__ src) {
    int i = blockIdx.x * blockDim.x + threadIdx.x;
    float4 v = ((const float4*)src)[i];
    __nv_bfloat16 h0 = __float2bfloat16(v.x), h1 = __float2bfloat16(v.y);
    __nv_bfloat16 h2 = __float2bfloat16(v.z), h3 = __float2bfloat16(v.w);
    __nv_bfloat162 hi0, hi1, lo0, lo1;
    hi0.x = h0; hi0.y = h1; hi1.x = h2; hi1.y = h3;
    lo0.x = __float2bfloat16(v.x - __bfloat162float(h0));
    lo0.y = __float2bfloat16(v.y - __bfloat162float(h1));
    lo1.x = __float2bfloat16(v.z - __bfloat162float(h2));
    lo1.y = __float2bfloat16(v.w - __bfloat162float(h3));
    size_t o = (size_t)i * 4;
    *(__nv_bfloat162*)&g_ahi[o] = hi0;
    *(__nv_bfloat162*)&g_ahi[o + 2] = hi1;
    *(__nv_bfloat162*)&g_alo[o] = lo0;
    *(__nv_bfloat162*)&g_alo[o + 2] = lo1;
}

// ---------------------------------------------------------------------------
// Tensor-core routed GEMM: C[b] = A[b] @ W[route[b]] via bf16x3 split,
// mma.sync.m16n8k16 + ldmatrix + cp.async double buffering.
// Block tile 128x128, BK=32, 8 warps (2x4), warp tile 64x32.
// smem tiles padded to 40 bf16 (80 B) per row -> conflict-free ldmatrix.
// ---------------------------------------------------------------------------
#define GBM 128
#define GBN 128
#define GBK 32
#define PADK 40
#define TILE_B (128 * PADK * 2)   // 10240 bytes per operand tile
#define STAGE_B (4 * TILE_B)      // Ah, Al, Bh, Bl

__global__ __launch_bounds__(256, 1) void gemm_mma(int proj,
                                                   float* __restrict__ C) {
    extern __shared__ char dsm[];
    uint32_t sbase = smem_u32(dsm);
    int b = blockIdx.z;
    int tM = blockIdx.y * GBM, tN = blockIdx.x * GBN;
    int tid = threadIdx.x, wid = tid >> 5, lane = tid & 31;
    int wm = wid >> 2, wn = wid & 3;

    const __nv_bfloat16* Ah = g_ahi + (size_t)b * LL * DD;
    const __nv_bfloat16* Al = g_alo + (size_t)b * LL * DD;
    size_t woff = ((size_t)proj * EE + g_routes[b]) * DD * DD;
    const __nv_bfloat16* Bh = g_wthi + woff;
    const __nv_bfloat16* Bl = g_wtlo + woff;

    float acc[4][4][4];
#pragma unroll
    for (int i = 0; i < 4; i++)
#pragma unroll
        for (int j = 0; j < 4; j++)
#pragma unroll
            for (int r = 0; r < 4; r++) acc[i][j][r] = 0.f;

    // ---- async stage loader: 2048 16B chunks (4 tiles x 128 rows x 4) ----
    const __nv_bfloat16* bases[4] = {Ah, Al, Bh, Bl};
#define LOAD_STAGE(kt, s)                                                    \
    do {                                                                     \
        int _k0 = (kt) * GBK;                                                \
        for (int i = tid; i < 2048; i += 256) {                              \
            int _t = i >> 9, _r = (i >> 2) & 127, _c = i & 3;                \
            int _row = (_t < 2 ? tM : tN) + _r;                              \
            const __nv_bfloat16* _src =                                      \
                bases[_t] + (size_t)_row * DD + _k0 + _c * 8;                \
            uint32_t _dst = sbase + (s) * STAGE_B + _t * TILE_B + _r * 80 +  \
                            _c * 16;                                         \
            CP_ASYNC16(_dst, _src);                                          \
        }                                                                    \
        CP_COMMIT();                                                         \
    } while (0)

    LOAD_STAGE(0, 0);
    const int NT = DD / GBK;  // 32
    for (int kt = 0; kt < NT; kt++) {
        int s = kt & 1;
        if (kt + 1 < NT) {
            LOAD_STAGE(kt + 1, s ^ 1);
            CP_WAIT1();
        } else {
            CP_WAIT0();
        }
        __syncthreads();

        uint32_t stb = sbase + s * STAGE_B;
#pragma unroll
        for (int ks = 0; ks < 2; ks++) {  // k-steps of 16 within BK=32
            int kc = ks * 16;
            // A fragments (hi and lo): 4 m-frags each
            uint32_t ah[4][4], al[4][4];
            {
                int arow = wm * 64 + (lane & 15);
                int acol = kc + (lane >> 4) * 8;
                uint32_t abase = stb + (uint32_t)arow * 80 + acol * 2;
#pragma unroll
                for (int am = 0; am < 4; am++) {
                    uint32_t ad = abase + am * 16 * 80;
                    LDSM_X4(ah[am][0], ah[am][1], ah[am][2], ah[am][3], ad);
                    LDSM_X4(al[am][0], al[am][1], al[am][2], al[am][3],
                            ad + TILE_B);
                }
            }
            // B fragments (hi and lo): 4 n-frags of 8, via 2 x4 loads each
            uint32_t bh[4][2], bl[4][2];
            {
                int nrow = wn * 32 + (lane & 7) + (lane >> 4) * 8;
                int bcol = kc + ((lane >> 3) & 1) * 8;
                uint32_t bbase =
                    stb + 2 * TILE_B + (uint32_t)nrow * 80 + bcol * 2;
#pragma unroll
                for (int bg = 0; bg < 2; bg++) {
                    uint32_t bd = bbase + bg * 16 * 80;
                    LDSM_X4(bh[bg * 2][0], bh[bg * 2][1], bh[bg * 2 + 1][0],
                            bh[bg * 2 + 1][1], bd);
                    LDSM_X4(bl[bg * 2][0], bl[bg * 2][1], bl[bg * 2 + 1][0],
                            bl[bg * 2 + 1][1], bd + TILE_B);
                }
            }
#pragma unroll
            for (int am = 0; am < 4; am++)
#pragma unroll
                for (int bn = 0; bn < 4; bn++) {
                    MMA_BF16(acc[am][bn], ah[am], bh[bn]);  // Ah*Bh
                    MMA_BF16(acc[am][bn], ah[am], bl[bn]);  // Ah*Bl
                    MMA_BF16(acc[am][bn], al[am], bh[bn]);  // Al*Bh
                }
        }
        __syncthreads();
    }

    // ---- epilogue: fragment -> C (fp32) ----
    float* Cb = C + (size_t)b * LL * DD;
    int qr = lane >> 2, qc = (lane & 3) * 2;
#pragma unroll
    for (int am = 0; am < 4; am++) {
        int row0 = tM + wm * 64 + am * 16 + qr;
#pragma unroll
        for (int bn = 0; bn < 4; bn++) {
            int col = tN + wn * 32 + bn * 8 + qc;
            *(float2*)&Cb[(size_t)row0 * DD + col] =
                make_float2(acc[am][bn][0], acc[am][bn][1]);
            *(float2*)&Cb[(size_t)(row0 + 8) * DD + col] =
                make_float2(acc[am][bn][2], acc[am][bn][3]);
        }
    }
#undef LOAD_STAGE
}

// ---------------------------------------------------------------------------
// RoPE (interleaved), in-place on g_q / g_k.
// ---------------------------------------------------------------------------
__global__ void rope_kernel() {
    int idx = blockIdx.x * blockDim.x + threadIdx.x;
    int total = BB * LL * HH * (HD / 2);
    if (idx >= total) return;
    int d2 = idx & 31;
    int h = (idx >> 5) & 15;
    int l = (idx >> 9) & 511;
    int b = idx >> 18;
    float inv = powf(10000.0f, -(float)d2 / 32.0f);
    float ang = (float)l * inv;
    float s, c;
    sincosf(ang, &s, &c);
    size_t base = ((size_t)(b * LL + l)) * DD + h * HD + 2 * d2;
    float2 q = *(float2*)&g_q[base];
    float2 k = *(float2*)&g_k[base];
    *(float2*)&g_q[base] = make_float2(q.x * c - q.y * s, q.y * c + q.x * s);
    *(float2*)&g_k[base] = make_float2(k.x * c - k.y * s, k.y * c + k.x * s);
}

// ---------------------------------------------------------------------------
// Flash-style causal attention (SIMT; next round's tensor-core target).
// ---------------------------------------------------------------------------
__global__ __launch_bounds__(256) void attn_kernel() {
    extern __shared__ float smem[];
    float* sQ = smem;
    float* sK = sQ + 64 * 65;
    float* sV = sK + 64 * 65;
    float* sP = sV + 64 * 64;
    int qt = blockIdx.x, h = blockIdx.y, b = blockIdx.z;
    int tid = threadIdx.x;
    const float scale = 0.125f;
    size_t hbase = ((size_t)b * LL) * DD + h * HD;

    for (int i = tid; i < 64 * 16; i += 256) {
        int r = i >> 4, cg = (i & 15) * 4;
        float4 v = *(const float4*)&g_q[hbase + (size_t)(qt * 64 + r) * DD + cg];
        sQ[r * 65 + cg + 0] = v.x;
        sQ[r * 65 + cg + 1] = v.y;
        sQ[r * 65 + cg + 2] = v.z;
        sQ[r * 65 + cg + 3] = v.w;
    }

    int r = tid >> 2;
    int c4 = tid & 3;
    int tx = tid & 15, ty = tid >> 4;
    float o[16];
#pragma unroll
    for (int i = 0; i < 16; i++) o[i] = 0.f;
    float m_i = -1e30f, l_i = 0.f;

    for (int kt = 0; kt <= qt; kt++) {
        __syncthreads();
        for (int i = tid; i < 64 * 16; i += 256) {
            int rr = i >> 4, cg = (i & 15) * 4;
            size_t g = hbase + (size_t)(kt * 64 + rr) * DD + cg;
            float4 kv = *(const float4*)&g_k[g];
            sK[rr * 65 + cg + 0] = kv.x;
            sK[rr * 65 + cg + 1] = kv.y;
            sK[rr * 65 + cg + 2] = kv.z;
            sK[rr * 65 + cg + 3] = kv.w;
            *(float4*)&sV[rr * 64 + cg] = *(const float4*)&g_v[g];
        }
        __syncthreads();

        float acc[4][4];
#pragma unroll
        for (int i = 0; i < 4; i++)
#pragma unroll
            for (int j = 0; j < 4; j++) acc[i][j] = 0.f;
        for (int kk = 0; kk < 64; kk++) {
            float a[4], bb[4];
#pragma unroll
            for (int i = 0; i < 4; i++) a[i] = sQ[(ty * 4 + i) * 65 + kk];
#pragma unroll
            for (int j = 0; j < 4; j++) bb[j] = sK[(tx * 4 + j) * 65 + kk];
#pragma unroll
            for (int i = 0; i < 4; i++)
#pragma unroll
                for (int j = 0; j < 4; j++) acc[i][j] += a[i] * bb[j];
        }
        bool diag = (kt == qt);
#pragma unroll
        for (int i = 0; i < 4; i++) {
            int sr = ty * 4 + i;
#pragma unroll
            for (int j = 0; j < 4; j++) {
                int sc = tx * 4 + j;
                float vv = acc[i][j] * scale;
                if (diag && sc > sr) vv = -1e30f;
                sP[sr * 65 + sc] = vv;
            }
        }
        __syncthreads();

        float mloc = -1e30f;
#pragma unroll
        for (int jj = 0; jj < 16; jj++)
            mloc = fmaxf(mloc, sP[r * 65 + c4 * 16 + jj]);
        mloc = fmaxf(mloc, __shfl_xor_sync(0xffffffffu, mloc, 1));
        mloc = fmaxf(mloc, __shfl_xor_sync(0xffffffffu, mloc, 2));
        float mnew = fmaxf(m_i, mloc);
        float alpha = __expf(m_i - mnew);
        float psum = 0.f;
#pragma unroll
        for (int jj = 0; jj < 16; jj++) {
            float p = __expf(sP[r * 65 + c4 * 16 + jj] - mnew);
            sP[r * 65 + c4 * 16 + jj] = p;
            psum += p;
        }
        psum += __shfl_xor_sync(0xffffffffu, psum, 1);
        psum += __shfl_xor_sync(0xffffffffu, psum, 2);
        l_i = l_i * alpha + psum;
        m_i = mnew;
#pragma unroll
        for (int i = 0; i < 16; i++) o[i] *= alpha;
        __syncwarp();

        for (int j = 0; j < 64; j++) {
            float p = sP[r * 65 + j];
            float4 v0 = *(const float4*)&sV[j * 64 + c4 * 16 + 0];
            float4 v1 = *(const float4*)&sV[j * 64 + c4 * 16 + 4];
            float4 v2 = *(const float4*)&sV[j * 64 + c4 * 16 + 8];
            float4 v3 = *(const float4*)&sV[j * 64 + c4 * 16 + 12];
            o[0] += p * v0.x;  o[1] += p * v0.y;  o[2] += p * v0.z;  o[3] += p * v0.w;
            o[4] += p * v1.x;  o[5] += p * v1.y;  o[6] += p * v1.z;  o[7] += p * v1.w;
            o[8] += p * v2.x;  o[9] += p * v2.y;  o[10] += p * v2.z; o[11] += p * v2.w;
            o[12] += p * v3.x; o[13] += p * v3.y; o[14] += p * v3.z; o[15] += p * v3.w;
        }
    }

    float invl = 1.0f / l_i;
    size_t obase = hbase + (size_t)(qt * 64 + r) * DD + c4 * 16;
#pragma unroll
    for (int i = 0; i < 16; i += 4)
        *(float4*)&g_ctx[obase + i] =
            make_float4(o[i] * invl, o[i + 1] * invl, o[i + 2] * invl,
                        o[i + 3] * invl);
}

// ---------------------------------------------------------------------------
extern "C" void kernel_launch(void* const* d_in, const int* in_sizes, int n_in,
                              void* d_out, int out_size) {
    (void)in_sizes; (void)n_in; (void)out_size;
    const float* x  = (const float*)d_in[0];
    const float* qw = (const float*)d_in[1];
    const float* kw = (const float*)d_in[2];
    const float* vw = (const float*)d_in[3];
    const float* ow = (const float*)d_in[4];
    const float* rw = (const float*)d_in[5];
    const float* rb = (const float*)d_in[6];
    float* out = (float*)d_out;
    float* probs = out + (size_t)BB * LL * DD;

    void *pq, *pk, *pv, *pc;
    cudaGetSymbolAddress(&pq, g_q);
    cudaGetSymbolAddress(&pk, g_k);
    cudaGetSymbolAddress(&pv, g_v);
    cudaGetSymbolAddress(&pc, g_ctx);

    int gsmem = 2 * STAGE_B;  // 81920
    static int smem_set = 0;
    if (!smem_set) {
        cudaFuncSetAttribute(gemm_mma, cudaFuncAttributeMaxDynamicSharedMemorySize,
                             gsmem);
        int asmem = (64 * 65 * 2 + 64 * 64 + 64 * 65) * (int)sizeof(float);
        cudaFuncSetAttribute(attn_kernel,
                             cudaFuncAttributeMaxDynamicSharedMemorySize, asmem);
        smem_set = 1;
    }

    router_kernel<<<BB, 256>>>(x, rw, rb, probs);
    wsplit_kernel<<<dim3(32, 32, 32), 256>>>(qw, kw, vw, ow);

    int splitBlocks = (BB * LL * DD / 4) / 256;
    asplit_kernel<<<splitBlocks, 256>>>(x);

    dim3 gg(DD / GBN, LL / GBM, BB);
    gemm_mma<<<gg, 256, gsmem>>>(0, (float*)pq);
    gemm_mma<<<gg, 256, gsmem>>>(1, (float*)pk);
    gemm_mma<<<gg, 256, gsmem>>>(2, (float*)pv);

    int pairs = BB * LL * HH * (HD / 2);
    rope_kernel<<<pairs / 256, 256>>>();

    int asmem = (64 * 65 * 2 + 64 * 64 + 64 * 65) * (int)sizeof(float);
    attn_kernel<<<dim3(LL / 64, HH, BB), 256, asmem>>>();

    asplit_kernel<<<splitBlocks, 256>>>((const float*)pc);
    gemm_mma<<<gg, 256, gsmem>>>(3, out);
}

// round 11
// speedup vs baseline: 2.7366x; 1.7980x over previous
#include <cuda_runtime.h>
#include <cuda_bf16.h>
#include <math.h>
#include <stdint.h>

#define BB 32
#define LL 512
#define DD 1024
#define EE 8
#define HH 16
#define HD 64

// ---------------- scratch globals (no allocation allowed) -------------------
__device__ float g_q[BB * LL * DD];
__device__ float g_k[BB * LL * DD];
__device__ float g_v[BB * LL * DD];
__device__ int g_routes[BB];
__device__ __nv_bfloat16 g_ahi[BB * LL * DD];   // A operand split (x, then ctx)
__device__ __nv_bfloat16 g_alo[BB * LL * DD];
__device__ __nv_bfloat16 g_wthi[4u * EE * DD * DD];  // W^T hi [proj][e][N][K]
__device__ __nv_bfloat16 g_wtlo[4u * EE * DD * DD];
__device__ __nv_bfloat16 g_qhi[BB * LL * DD];   // post-RoPE splits
__device__ __nv_bfloat16 g_qlo[BB * LL * DD];
__device__ __nv_bfloat16 g_khi[BB * LL * DD];
__device__ __nv_bfloat16 g_klo[BB * LL * DD];
__device__ __nv_bfloat16 g_vhi[BB * LL * DD];
__device__ __nv_bfloat16 g_vlo[BB * LL * DD];

// ---------------- PTX helpers (family-agnostic sm_80+ subset) ---------------
__device__ __forceinline__ uint32_t smem_u32(const void* p) {
    uint32_t a;
    asm("{ .reg .u64 t; cvta.to.shared.u64 t, %1; cvt.u32.u64 %0, t; }"
        : "=r"(a) : "l"(p));
    return a;
}
#define CP_ASYNC16(dst, src) \
    asm volatile("cp.async.cg.shared.global [%0], [%1], 16;" \
                 :: "r"(dst), "l"(src))
#define CP_COMMIT() asm volatile("cp.async.commit_group;" ::: "memory")
#define CP_WAIT1() asm volatile("cp.async.wait_group 1;" ::: "memory")
#define CP_WAIT0() asm volatile("cp.async.wait_group 0;" ::: "memory")

#define LDSM_X4(r0, r1, r2, r3, a) \
    asm volatile("ldmatrix.sync.aligned.m8n8.x4.shared.b16 {%0,%1,%2,%3}, [%4];" \
                 : "=r"(r0), "=r"(r1), "=r"(r2), "=r"(r3) : "r"(a))
#define LDSM_X4_T(r0, r1, r2, r3, a) \
    asm volatile("ldmatrix.sync.aligned.m8n8.x4.trans.shared.b16 {%0,%1,%2,%3}, [%4];" \
                 : "=r"(r0), "=r"(r1), "=r"(r2), "=r"(r3) : "r"(a))

#define MMA_BF16(c, a, b) \
    asm volatile( \
        "mma.sync.aligned.m16n8k16.row.col.f32.bf16.bf16.f32 " \
        "{%0,%1,%2,%3}, {%4,%5,%6,%7}, {%8,%9}, {%0,%1,%2,%3};" \
        : "+f"((c)[0]), "+f"((c)[1]), "+f"((c)[2]), "+f"((c)[3]) \
        : "r"((a)[0]), "r"((a)[1]), "r"((a)[2]), "r"((a)[3]), \
          "r"((b)[0]), "r"((b)[1]))

__device__ __forceinline__ uint32_t pack_bf2(float a, float b) {
    __nv_bfloat162 t = __floats2bfloat162_rn(a, b);
    return *(uint32_t*)&t;
}

// ---------------------------------------------------------------------------
// Router
// ---------------------------------------------------------------------------
__global__ void router_kernel(const float* __restrict__ x,
                              const float* __restrict__ rw,
                              const float* __restrict__ rb,
                              float* __restrict__ probs) {
    int b = blockIdx.x;
    __shared__ float mean[DD];
    __shared__ float logits[EE];
    const float* xb = x + (size_t)b * LL * DD;
    for (int d = threadIdx.x; d < DD; d += blockDim.x) {
        float s = 0.f;
        for (int l = 0; l < LL; l++) s += xb[(size_t)l * DD + d];
        mean[d] = s * (1.0f / LL);
    }
    __syncthreads();
    int w = threadIdx.x >> 5, lane = threadIdx.x & 31;
    if (w < EE) {
        float s = 0.f;
        for (int d = lane; d < DD; d += 32) s += mean[d] * rw[d * EE + w];
        for (int o = 16; o; o >>= 1) s += __shfl_xor_sync(0xffffffffu, s, o);
        if (lane == 0) logits[w] = s + rb[w];
    }
    __syncthreads();
    if (threadIdx.x == 0) {
        float mx = logits[0];
        int am = 0;
        for (int e = 1; e < EE; e++)
            if (logits[e] > mx) { mx = logits[e]; am = e; }
        float ex[EE], den = 0.f;
        for (int e = 0; e < EE; e++) { ex[e] = expf(logits[e] - mx); den += ex[e]; }
        float inv = 1.0f / den;
        for (int e = 0; e < EE; e++) probs[b * EE + e] = ex[e] * inv;
        g_routes[b] = am;
    }
}

// ---------------------------------------------------------------------------
// W transpose + bf16 split: Wt[n][k] = W[k][n] -> (hi, lo)
// ---------------------------------------------------------------------------
__global__ void wsplit_kernel(const float* __restrict__ qw,
                              const float* __restrict__ kw,
                              const float* __restrict__ vw,
                              const float* __restrict__ ow) {
    __shared__ float t[32][33];
    int m = blockIdx.z;
    int p = m >> 3, e = m & 7;
    const float* W = (p == 0 ? qw : p == 1 ? kw : p == 2 ? vw : ow) +
                     (size_t)e * DD * DD;
    int n0 = blockIdx.x * 32, k0 = blockIdx.y * 32;
    int tx = threadIdx.x & 31, ty = threadIdx.x >> 5;
#pragma unroll
    for (int i = 0; i < 32; i += 8)
        t[ty + i][tx] = W[(size_t)(k0 + ty + i) * DD + n0 + tx];
    __syncthreads();
    size_t dbase = (size_t)m * DD * DD;
#pragma unroll
    for (int i = 0; i < 32; i += 8) {
        float a = t[tx][ty + i];
        __nv_bfloat16 hi = __float2bfloat16(a);
        __nv_bfloat16 lo = __float2bfloat16(a - __bfloat162float(hi));
        size_t di = dbase + (size_t)(n0 + ty + i) * DD + k0 + tx;
        g_wthi[di] = hi;
        g_wtlo[di] = lo;
    }
}

// ---------------------------------------------------------------------------
// A-operand bf16 split (x). 4 floats / thread.
// ---------------------------------------------------------------------------
__global__ void asplit_kernel(const float* __restrict__ src) {
    int i = blockIdx.x * blockDim.x + threadIdx.x;
    float4 v = ((const float4*)src)[i];
    __nv_bfloat16 h0 = __float2bfloat16(v.x), h1 = __float2bfloat16(v.y);
    __nv_bfloat16 h2 = __float2bfloat16(v.z), h3 = __float2bfloat16(v.w);
    __nv_bfloat162 hi0, hi1, lo0, lo1;
    hi0.x = h0; hi0.y = h1; hi1.x = h2; hi1.y = h3;
    lo0.x = __float2bfloat16(v.x - __bfloat162float(h0));
    lo0.y = __float2bfloat16(v.y - __bfloat162float(h1));
    lo1.x = __float2bfloat16(v.z - __bfloat162float(h2));
    lo1.y = __float2bfloat16(v.w - __bfloat162float(h3));
    size_t o = (size_t)i * 4;
    *(__nv_bfloat162*)&g_ahi[o] = hi0;
    *(__nv_bfloat162*)&g_ahi[o + 2] = hi1;
    *(__nv_bfloat162*)&g_alo[o] = lo0;
    *(__nv_bfloat162*)&g_alo[o + 2] = lo1;
}

// ---------------------------------------------------------------------------
// Tensor-core routed GEMM (R7-proven — 317us, tensor=53%)
// ---------------------------------------------------------------------------
#define GBM 128
#define GBN 128
#define GBK 32
#define PADK 40
#define TILE_B (128 * PADK * 2)
#define STAGE_B (4 * TILE_B)

__global__ __launch_bounds__(256, 1) void gemm_mma(int proj,
                                                   float* __restrict__ C) {
    extern __shared__ char dsm[];
    uint32_t sbase = smem_u32(dsm);
    int b = blockIdx.z;
    int tM = blockIdx.y * GBM, tN = blockIdx.x * GBN;
    int tid = threadIdx.x, wid = tid >> 5, lane = tid & 31;
    int wm = wid >> 2, wn = wid & 3;

    const __nv_bfloat16* Ah = g_ahi + (size_t)b * LL * DD;
    const __nv_bfloat16* Al = g_alo + (size_t)b * LL * DD;
    size_t woff = ((size_t)proj * EE + g_routes[b]) * DD * DD;
    const __nv_bfloat16* Bh = g_wthi + woff;
    const __nv_bfloat16* Bl = g_wtlo + woff;

    float acc[4][4][4];
#pragma unroll
    for (int i = 0; i < 4; i++)
#pragma unroll
        for (int j = 0; j < 4; j++)
#pragma unroll
            for (int r = 0; r < 4; r++) acc[i][j][r] = 0.f;

    const __nv_bfloat16* bases[4] = {Ah, Al, Bh, Bl};
#define LOAD_STAGE(kt, s)                                                    \
    do {                                                                     \
        int _k0 = (kt) * GBK;                                                \
        for (int i = tid; i < 2048; i += 256) {                              \
            int _t = i >> 9, _r = (i >> 2) & 127, _c = i & 3;                \
            int _row = (_t < 2 ? tM : tN) + _r;                              \
            const __nv_bfloat16* _src =                                      \
                bases[_t] + (size_t)_row * DD + _k0 + _c * 8;                \
            uint32_t _dst = sbase + (s) * STAGE_B + _t * TILE_B + _r * 80 +  \
                            _c * 16;                                         \
            CP_ASYNC16(_dst, _src);                                          \
        }                                                                    \
        CP_COMMIT();                                                         \
    } while (0)

    LOAD_STAGE(0, 0);
    const int NT = DD / GBK;
    for (int kt = 0; kt < NT; kt++) {
        int s = kt & 1;
        if (kt + 1 < NT) {
            LOAD_STAGE(kt + 1, s ^ 1);
            CP_WAIT1();
        } else {
            CP_WAIT0();
        }
        __syncthreads();

        uint32_t stb = sbase + s * STAGE_B;
#pragma unroll
        for (int ks = 0; ks < 2; ks++) {
            int kc = ks * 16;
            uint32_t ah[4][4], al[4][4];
            {
                int arow = wm * 64 + (lane & 15);
                int acol = kc + (lane >> 4) * 8;
                uint32_t abase = stb + (uint32_t)arow * 80 + acol * 2;
#pragma unroll
                for (int am = 0; am < 4; am++) {
                    uint32_t ad = abase + am * 16 * 80;
                    LDSM_X4(ah[am][0], ah[am][1], ah[am][2], ah[am][3], ad);
                    LDSM_X4(al[am][0], al[am][1], al[am][2], al[am][3],
                            ad + TILE_B);
                }
            }
            uint32_t bh[4][2], bl[4][2];
            {
                int nrow = wn * 32 + (lane & 7) + (lane >> 4) * 8;
                int bcol = kc + ((lane >> 3) & 1) * 8;
                uint32_t bbase =
                    stb + 2 * TILE_B + (uint32_t)nrow * 80 + bcol * 2;
#pragma unroll
                for (int bg = 0; bg < 2; bg++) {
                    uint32_t bd = bbase + bg * 16 * 80;
                    LDSM_X4(bh[bg * 2][0], bh[bg * 2][1], bh[bg * 2 + 1][0],
                            bh[bg * 2 + 1][1], bd);
                    LDSM_X4(bl[bg * 2][0], bl[bg * 2][1], bl[bg * 2 + 1][0],
                            bl[bg * 2 + 1][1], bd + TILE_B);
                }
            }
#pragma unroll
            for (int am = 0; am < 4; am++)
#pragma unroll
                for (int bn = 0; bn < 4; bn++) {
                    MMA_BF16(acc[am][bn], ah[am], bh[bn]);
                    MMA_BF16(acc[am][bn], ah[am], bl[bn]);
                    MMA_BF16(acc[am][bn], al[am], bh[bn]);
                }
        }
        __syncthreads();
    }

    float* Cb = C + (size_t)b * LL * DD;
    int qr = lane >> 2, qc = (lane & 3) * 2;
#pragma unroll
    for (int am = 0; am < 4; am++) {
        int row0 = tM + wm * 64 + am * 16 + qr;
#pragma unroll
        for (int bn = 0; bn < 4; bn++) {
            int col = tN + wn * 32 + bn * 8 + qc;
            *(float2*)&Cb[(size_t)row0 * DD + col] =
                make_float2(acc[am][bn][0], acc[am][bn][1]);
            *(float2*)&Cb[(size_t)(row0 + 8) * DD + col] =
                make_float2(acc[am][bn][2], acc[am][bn][3]);
        }
    }
#undef LOAD_STAGE
}

// ---------------------------------------------------------------------------
// RoPE + bf16 hi/lo split of Q, K, V (fp32 gemm outputs -> 6 bf16 arrays).
// ---------------------------------------------------------------------------
__global__ void rope_split_kernel() {
    int idx = blockIdx.x * blockDim.x + threadIdx.x;
    int total = BB * LL * HH * (HD / 2);
    if (idx >= total) return;
    int d2 = idx & 31;
    int h = (idx >> 5) & 15;
    int l = (idx >> 9) & 511;
    int b = idx >> 18;
    float inv = powf(10000.0f, -(float)d2 / 32.0f);
    float ang = (float)l * inv;
    float s, c;
    sincosf(ang, &s, &c);
    size_t base = ((size_t)(b * LL + l)) * DD + h * HD + 2 * d2;
    float2 q = *(float2*)&g_q[base];
    float2 k = *(float2*)&g_k[base];
    float2 v = *(float2*)&g_v[base];
    float qx = q.x * c - q.y * s, qy = q.y * c + q.x * s;
    float kx = k.x * c - k.y * s, ky = k.y * c + k.x * s;

    __nv_bfloat16 h0, h1;
    __nv_bfloat162 hv, lv;
#define SPLIT_STORE(ax, ay, AH, AL)                      \
    h0 = __float2bfloat16(ax); h1 = __float2bfloat16(ay);\
    hv.x = h0; hv.y = h1;                                \
    lv.x = __float2bfloat16((ax) - __bfloat162float(h0));\
    lv.y = __float2bfloat16((ay) - __bfloat162float(h1));\
    *(__nv_bfloat162*)&AH[base] = hv;                    \
    *(__nv_bfloat162*)&AL[base] = lv;
    SPLIT_STORE(qx, qy, g_qhi, g_qlo)
    SPLIT_STORE(kx, ky, g_khi, g_klo)
    SPLIT_STORE(v.x, v.y, g_vhi, g_vlo)
#undef SPLIT_STORE
}

// ---------------------------------------------------------------------------
// Tensor-core flash attention, bf16x3 split everywhere.
// Block: 4 warps, 64 q-rows (16/warp). K/V double-buffered via cp.async.
// Writes O directly as bf16 hi/lo into g_ahi/g_alo for the final GEMM.
// ---------------------------------------------------------------------------
#define AT_PAD 144            // smem row stride bytes (72 bf16)
#define AT_TILE (64 * AT_PAD) // 9216 B per 64x64 bf16 tile

__global__ __launch_bounds__(128) void attn_mma() {
    extern __shared__ char smraw[];
    uint32_t sb = smem_u32(smraw);
    int qt = blockIdx.x, h = blockIdx.y, b = blockIdx.z;
    int tid = threadIdx.x, wid = tid >> 5, lane = tid & 31;
    size_t hoff = ((size_t)b * LL) * DD + h * HD;

    // smem layout: [Qh][Ql] then stage s in {0,1}: [Kh][Kl][Vh][Vl]
    {
        int q0 = qt * 64;
        for (int i = tid; i < 1024; i += 128) {
            int t = i >> 9, r = (i >> 3) & 63, c = i & 7;
            const __nv_bfloat16* src =
                (t ? g_qlo : g_qhi) + hoff + (size_t)(q0 + r) * DD + c * 8;
            CP_ASYNC16(sb + t * AT_TILE + r * AT_PAD + c * 16, src);
        }
        CP_COMMIT();
    }
    const __nv_bfloat16* kvsrc[4] = {g_khi, g_klo, g_vhi, g_vlo};
#define LOAD_KV(kt, s)                                                        \
    do {                                                                      \
        int _k0 = (kt) * 64;                                                  \
        uint32_t _stb = sb + 2 * AT_TILE + (s) * 4 * AT_TILE;                 \
        for (int i = tid; i < 2048; i += 128) {                               \
            int _t = i >> 9, _r = (i >> 3) & 63, _c = i & 7;                  \
            const __nv_bfloat16* _src =                                       \
                kvsrc[_t] + hoff + (size_t)(_k0 + _r) * DD + _c * 8;          \
            CP_ASYNC16(_stb + _t * AT_TILE + _r * AT_PAD + _c * 16, _src);    \
        }                                                                     \
        CP_COMMIT();                                                          \
    } while (0)

    LOAD_KV(0, 0);
    CP_WAIT1();  // Q group done (KV0 may be in flight)
    __syncthreads();

    // Q fragments (A operand), preloaded for whole mainloop
    uint32_t qh[4][4], ql[4][4];
    {
        uint32_t abase = sb + (uint32_t)(wid * 16 + (lane & 15)) * AT_PAD +
                         (lane >> 4) * 16;
#pragma unroll
        for (int ks = 0; ks < 4; ks++) {
            uint32_t ad = abase + ks * 32;
            LDSM_X4(qh[ks][0], qh[ks][1], qh[ks][2], qh[ks][3], ad);
            LDSM_X4(ql[ks][0], ql[ks][1], ql[ks][2], ql[ks][3], ad + AT_TILE);
        }
    }

    float o[8][4];
#pragma unroll
    for (int i = 0; i < 8; i++)
#pragma unroll
        for (int j = 0; j < 4; j++) o[i][j] = 0.f;
    float m0 = -1e30f, m1 = -1e30f, l0 = 0.f, l1 = 0.f;
    int qrow0 = qt * 64 + wid * 16 + (lane >> 2);

    for (int kt = 0; kt <= qt; kt++) {
        int s = kt & 1;
        if (kt < qt) { LOAD_KV(kt + 1, s ^ 1); CP_WAIT1(); } else { CP_WAIT0(); }
        __syncthreads();
        uint32_t stb = sb + 2 * AT_TILE + s * 4 * AT_TILE;

        // ---- S = Q K^T (bf16x3) ----
        float sacc[8][4];
#pragma unroll
        for (int i = 0; i < 8; i++)
#pragma unroll
            for (int j = 0; j < 4; j++) sacc[i][j] = 0.f;
#pragma unroll
        for (int ks = 0; ks < 4; ks++) {
            uint32_t kh[8][2], kl[8][2];
            uint32_t bb = stb +
                (uint32_t)((lane & 7) + ((lane >> 4) & 1) * 8) * AT_PAD +
                ks * 32 + ((lane >> 3) & 1) * 16;
#pragma unroll
            for (int nf2 = 0; nf2 < 4; nf2++) {
                uint32_t bd = bb + nf2 * 16 * AT_PAD;
                LDSM_X4(kh[nf2 * 2][0], kh[nf2 * 2][1], kh[nf2 * 2 + 1][0],
                        kh[nf2 * 2 + 1][1], bd);
                LDSM_X4(kl[nf2 * 2][0], kl[nf2 * 2][1], kl[nf2 * 2 + 1][0],
                        kl[nf2 * 2 + 1][1], bd + AT_TILE);
            }
#pragma unroll
            for (int nf = 0; nf < 8; nf++) {
                MMA_BF16(sacc[nf], qh[ks], kh[nf]);
                MMA_BF16(sacc[nf], qh[ks], kl[nf]);
                MMA_BF16(sacc[nf], ql[ks], kh[nf]);
            }
        }

        // ---- online softmax ----
        const float scale = 0.125f;
        bool diag = (kt == qt);
        float mx0 = m0, mx1 = m1;
#pragma unroll
        for (int nf = 0; nf < 8; nf++) {
            int colb = kt * 64 + nf * 8 + (lane & 3) * 2;
#pragma unroll
            for (int i = 0; i < 4; i++) {
                float v = sacc[nf][i] * scale;
                if (diag) {
                    int col = colb + (i & 1);
                    int row = qrow0 + ((i >> 1) << 3);
                    if (col > row) v = -1e30f;
                }
                sacc[nf][i] = v;
                if (i < 2) mx0 = fmaxf(mx0, v);
                else       mx1 = fmaxf(mx1, v);
            }
        }
        mx0 = fmaxf(mx0, __shfl_xor_sync(0xffffffffu, mx0, 1));
        mx0 = fmaxf(mx0, __shfl_xor_sync(0xffffffffu, mx0, 2));
        mx1 = fmaxf(mx1, __shfl_xor_sync(0xffffffffu, mx1, 1));
        mx1 = fmaxf(mx1, __shfl_xor_sync(0xffffffffu, mx1, 2));
        float a0 = __expf(m0 - mx0), a1 = __expf(m1 - mx1);
        m0 = mx0; m1 = mx1;
        float s0 = 0.f, s1 = 0.f;
#pragma unroll
        for (int nf = 0; nf < 8; nf++) {
            float p0 = __expf(sacc[nf][0] - m0);
            float p1 = __expf(sacc[nf][1] - m0);
            float p2 = __expf(sacc[nf][2] - m1);
            float p3 = __expf(sacc[nf][3] - m1);
            sacc[nf][0] = p0; sacc[nf][1] = p1;
            sacc[nf][2] = p2; sacc[nf][3] = p3;
            s0 += p0 + p1; s1 += p2 + p3;
        }
        s0 += __shfl_xor_sync(0xffffffffu, s0, 1);
        s0 += __shfl_xor_sync(0xffffffffu, s0, 2);
        s1 += __shfl_xor_sync(0xffffffffu, s1, 1);
        s1 += __shfl_xor_sync(0xffffffffu, s1, 2);
        l0 = l0 * a0 + s0;
        l1 = l1 * a1 + s1;
#pragma unroll
        for (int nf = 0; nf < 8; nf++) {
            o[nf][0] *= a0; o[nf][1] *= a0;
            o[nf][2] *= a1; o[nf][3] *= a1;
        }

        // ---- O += P V (bf16x3) ----
#pragma unroll
        for (int ks = 0; ks < 4; ks++) {
            uint32_t pha[4], pla[4];
            {
                float* c0 = sacc[2 * ks];
                float* c1 = sacc[2 * ks + 1];
                float e[8] = {c0[0], c0[1], c0[2], c0[3],
                              c1[0], c1[1], c1[2], c1[3]};
                float eh[8], el[8];
#pragma unroll
                for (int j = 0; j < 8; j++) {
                    __nv_bfloat16 hb = __float2bfloat16(e[j]);
                    eh[j] = __bfloat162float(hb);
                    el[j] = e[j] - eh[j];
                }
                pha[0] = pack_bf2(eh[0], eh[1]); pha[1] = pack_bf2(eh[2], eh[3]);
                pha[2] = pack_bf2(eh[4], eh[5]); pha[3] = pack_bf2(eh[6], eh[7]);
                pla[0] = pack_bf2(el[0], el[1]); pla[1] = pack_bf2(el[2], el[3]);
                pla[2] = pack_bf2(el[4], el[5]); pla[3] = pack_bf2(el[6], el[7]);
            }
            uint32_t vb = stb + 2 * AT_TILE +
                (uint32_t)(ks * 16 + (lane & 7) + ((lane >> 3) & 1) * 8) * AT_PAD +
                ((lane >> 4) & 1) * 16;
#pragma unroll
            for (int nf2 = 0; nf2 < 4; nf2++) {
                uint32_t vh[2][2], vl[2][2];
                uint32_t vd = vb + nf2 * 32;
                LDSM_X4_T(vh[0][0], vh[0][1], vh[1][0], vh[1][1], vd);
                LDSM_X4_T(vl[0][0], vl[0][1], vl[1][0], vl[1][1], vd + AT_TILE);
#pragma unroll
                for (int g = 0; g < 2; g++) {
                    MMA_BF16(o[nf2 * 2 + g], pha, vh[g]);
                    MMA_BF16(o[nf2 * 2 + g], pha, vl[g]);
                    MMA_BF16(o[nf2 * 2 + g], pla, vh[g]);
                }
            }
        }
        __syncthreads();  // stage consumers done before next prefetch overwrite
    }

    // ---- epilogue: O/l -> bf16 hi/lo into g_ahi/g_alo ----
    float il0 = 1.0f / l0, il1 = 1.0f / l1;
    size_t ob0 = hoff + (size_t)(qt * 64 + wid * 16 + (lane >> 2)) * DD +
                 (lane & 3) * 2;
    size_t ob1 = ob0 + (size_t)8 * DD;
#pragma unroll
    for (int nf = 0; nf < 8; nf++) {
        float v0 = o[nf][0] * il0, v1 = o[nf][1] * il0;
        float v2 = o[nf][2] * il1, v3 = o[nf][3] * il1;
        __nv_bfloat16 h0 = __float2bfloat16(v0), h1 = __float2bfloat16(v1);
        __nv_bfloat16 h2 = __float2bfloat16(v2), h3 = __float2bfloat16(v3);
        __nv_bfloat162 hv, lv;
        hv.x = h0; hv.y = h1;
        lv.x = __float2bfloat16(v0 - __bfloat162float(h0));
        lv.y = __float2bfloat16(v1 - __bfloat162float(h1));
        *(__nv_bfloat162*)&g_ahi[ob0 + nf * 8] = hv;
        *(__nv_bfloat162*)&g_alo[ob0 + nf * 8] = lv;
        hv.x = h2; hv.y = h3;
        lv.x = __float2bfloat16(v2 - __bfloat162float(h2));
        lv.y = __float2bfloat16(v3 - __bfloat162float(h3));
        *(__nv_bfloat162*)&g_ahi[ob1 + nf * 8] = hv;
        *(__nv_bfloat162*)&g_alo[ob1 + nf * 8] = lv;
    }
#undef LOAD_KV
}

// ---------------------------------------------------------------------------
extern "C" void kernel_launch(void* const* d_in, const int* in_sizes, int n_in,
                              void* d_out, int out_size) {
    (void)in_sizes; (void)n_in; (void)out_size;
    const float* x  = (const float*)d_in[0];
    const float* qw = (const float*)d_in[1];
    const float* kw = (const float*)d_in[2];
    const float* vw = (const float*)d_in[3];
    const float* ow = (const float*)d_in[4];
    const float* rw = (const float*)d_in[5];
    const float* rb = (const float*)d_in[6];
    float* out = (float*)d_out;
    float* probs = out + (size_t)BB * LL * DD;

    void *pq, *pk, *pv;
    cudaGetSymbolAddress(&pq, g_q);
    cudaGetSymbolAddress(&pk, g_k);
    cudaGetSymbolAddress(&pv, g_v);

    int gsmem = 2 * STAGE_B;       // 81920
    int asmem = 10 * AT_TILE;      // 92160
    static int smem_set = 0;
    if (!smem_set) {
        cudaFuncSetAttribute(gemm_mma,
                             cudaFuncAttributeMaxDynamicSharedMemorySize, gsmem);
        cudaFuncSetAttribute(attn_mma,
                             cudaFuncAttributeMaxDynamicSharedMemorySize, asmem);
        smem_set = 1;
    }

    router_kernel<<<BB, 256>>>(x, rw, rb, probs);
    wsplit_kernel<<<dim3(32, 32, 32), 256>>>(qw, kw, vw, ow);

    int splitBlocks = (BB * LL * DD / 4) / 256;
    asplit_kernel<<<splitBlocks, 256>>>(x);

    dim3 gg(DD / GBN, LL / GBM, BB);
    gemm_mma<<<gg, 256, gsmem>>>(0, (float*)pq);
    gemm_mma<<<gg, 256, gsmem>>>(1, (float*)pk);
    gemm_mma<<<gg, 256, gsmem>>>(2, (float*)pv);

    int pairs = BB * LL * HH * (HD / 2);
    rope_split_kernel<<<pairs / 256, 256>>>();

    attn_mma<<<dim3(LL / 64, HH, BB), 128, asmem>>>();

    gemm_mma<<<gg, 256, gsmem>>>(3, out);
}